// round 2
// baseline (speedup 1.0000x reference)
#include <cuda_runtime.h>
#include <math.h>

#define N_RAYS   4096
#define N_SAMP   192
#define S_TOTAL  (N_RAYS * N_SAMP)   // 786432
#define TILE_M   128
#define A_W      135                  // 0-127 act | 128-130 pos | 131-133 view | 134 pad (odd width: no bank conflict on strided row loads)
#define NT       256

// smem: A tile + weight staging (max 131x128) + bias staging (128)
#define SMEM_FLOATS (TILE_M * A_W + 131 * 128 + 128)
#define SMEM_BYTES  (SMEM_FLOATS * 4)

__device__ __forceinline__ void copyw(float* dst, const float* __restrict__ src, int n) {
    const float4* s4 = (const float4*)src;
    float4* d4 = (float4*)dst;
    int n4 = n >> 2;
    for (int i = threadIdx.x; i < n4; i += NT) d4[i] = s4[i];
}
__device__ __forceinline__ void copyb(float* dst, const float* __restrict__ src, int n) {
    for (int i = threadIdx.x; i < n; i += NT) dst[i] = src[i];
}

// GEMM: [128 rows x K] @ [K x 128] + bias, ReLU, writeback into A cols 0..127.
// a_base: column offset in A where the K inputs start (128 for layer0 reading pos).
// skip:   added to A-column index for k>=128 (r-layer gathers view at cols 131-133).
__device__ __forceinline__ void dense128(float* A, const float* Wt, const float* Bs,
                                         int K, int a_base, int skip) {
    const int tx = threadIdx.x & 15;   // 16 col-groups of 8
    const int ty = threadIdx.x >> 4;   // 16 row-groups; rows ty + 16*j
    float acc[8][8];
#pragma unroll
    for (int i = 0; i < 8; i++) {
        float bv = Bs[tx * 8 + i];
#pragma unroll
        for (int j = 0; j < 8; j++) acc[j][i] = bv;
    }
#pragma unroll 4
    for (int k = 0; k < K; k++) {
        int ka = a_base + k + ((k >= 128) ? skip : 0);
        float a[8];
#pragma unroll
        for (int j = 0; j < 8; j++) a[j] = A[(ty + 16 * j) * A_W + ka];
        float4 b0v = *(const float4*)&Wt[k * 128 + tx * 8];
        float4 b1v = *(const float4*)&Wt[k * 128 + tx * 8 + 4];
        float b[8] = {b0v.x, b0v.y, b0v.z, b0v.w, b1v.x, b1v.y, b1v.z, b1v.w};
#pragma unroll
        for (int j = 0; j < 8; j++)
#pragma unroll
            for (int i = 0; i < 8; i++)
                acc[j][i] = fmaf(a[j], b[i], acc[j][i]);
    }
    __syncthreads();   // all reads of A / Wt done before overwrite
#pragma unroll
    for (int j = 0; j < 8; j++)
#pragma unroll
        for (int i = 0; i < 8; i++)
            A[(ty + 16 * j) * A_W + tx * 8 + i] = fmaxf(acc[j][i], 0.f);
    __syncthreads();
}

// r-layer: [128 x 131] @ [131 x 64] + br, ReLU -> A cols 0..63.
// Inputs: features at A cols 0..127, view at cols 131..133.
__device__ __forceinline__ void dense_r(float* A, const float* Wt, const float* Bs) {
    const int tx = threadIdx.x & 7;    // 8 col-groups of 8 (N=64)
    const int ty = threadIdx.x >> 3;   // 32 row-groups; rows ty + 32*j
    float acc[4][8];
#pragma unroll
    for (int i = 0; i < 8; i++) {
        float bv = Bs[tx * 8 + i];
#pragma unroll
        for (int j = 0; j < 4; j++) acc[j][i] = bv;
    }
#pragma unroll 4
    for (int k = 0; k < 131; k++) {
        int ka = (k < 128) ? k : k + 3;
        float a[4];
#pragma unroll
        for (int j = 0; j < 4; j++) a[j] = A[(ty + 32 * j) * A_W + ka];
        float4 b0v = *(const float4*)&Wt[k * 64 + tx * 8];
        float4 b1v = *(const float4*)&Wt[k * 64 + tx * 8 + 4];
        float b[8] = {b0v.x, b0v.y, b0v.z, b0v.w, b1v.x, b1v.y, b1v.z, b1v.w};
#pragma unroll
        for (int j = 0; j < 4; j++)
#pragma unroll
            for (int i = 0; i < 8; i++)
                acc[j][i] = fmaf(a[j], b[i], acc[j][i]);
    }
    __syncthreads();
#pragma unroll
    for (int j = 0; j < 4; j++)
#pragma unroll
        for (int i = 0; i < 8; i++)
            A[(ty + 32 * j) * A_W + tx * 8 + i] = fmaxf(acc[j][i], 0.f);
    __syncthreads();
}

__global__ void __launch_bounds__(NT, 1) nerf_fused_kernel(
    const float* __restrict__ x,
    const float* __restrict__ w0, const float* __restrict__ b0,
    const float* __restrict__ w1, const float* __restrict__ b1,
    const float* __restrict__ w2, const float* __restrict__ b2,
    const float* __restrict__ w3, const float* __restrict__ b3,
    const float* __restrict__ wd, const float* __restrict__ bd,
    const float* __restrict__ wf, const float* __restrict__ bf,
    const float* __restrict__ wr, const float* __restrict__ br,
    const float* __restrict__ wo, const float* __restrict__ bo,
    float* __restrict__ out) {
    extern __shared__ float smem[];
    float* A  = smem;                    // TILE_M * A_W
    float* Wt = A + TILE_M * A_W;        // up to 131*128
    float* Bs = Wt + 131 * 128;          // 128

    const int tid = threadIdx.x;
    const int s0 = blockIdx.x * TILE_M;

    // Stage x tile: pos -> cols 128..130, view -> cols 131..133
    for (int i = tid; i < TILE_M * 6; i += NT) {
        int r = i / 6, c = i % 6;
        A[r * A_W + 128 + c] = x[(size_t)(s0 + r) * 6 + c];
    }
    __syncthreads();

    // Layer 0: pos(3) -> 128
    copyw(Wt, w0, 3 * 128);  copyb(Bs, b0, 128);
    __syncthreads();
    dense128(A, Wt, Bs, 3, 128, 0);

    // Layer 1: 128 -> 128
    copyw(Wt, w1, 128 * 128); copyb(Bs, b1, 128);
    __syncthreads();
    dense128(A, Wt, Bs, 128, 0, 0);

    // Layer 2: [h, pos](131) -> 128  (pos contiguous at cols 128..130)
    copyw(Wt, w2, 131 * 128); copyb(Bs, b2, 128);
    __syncthreads();
    dense128(A, Wt, Bs, 131, 0, 0);

    // Layer 3: 128 -> 128
    copyw(Wt, w3, 128 * 128); copyb(Bs, b3, 128);
    __syncthreads();
    dense128(A, Wt, Bs, 128, 0, 0);

    // Stage wf (features) and wd (density head) together; bf -> Bs
    copyw(Wt, wf, 128 * 128);
    copyw(Wt + 128 * 128, wd, 128);
    copyb(Bs, bf, 128);
    __syncthreads();

    // Density: relu(h3 @ wd + bd), one row per thread (tid < 128), BEFORE A is overwritten
    if (tid < TILE_M) {
        const float* wds = Wt + 128 * 128;
        float d = bd[0];
#pragma unroll 8
        for (int k = 0; k < 128; k++) d = fmaf(A[tid * A_W + k], wds[k], d);
        out[3 * S_TOTAL + s0 + tid] = fmaxf(d, 0.f);
    }
    // Features: relu(h3 @ wf + bf) -> A cols 0..127 (internal sync orders density reads before writeback)
    dense128(A, Wt, Bs, 128, 0, 0);

    // r-layer: [features, view](131) -> 64
    copyw(Wt, wr, 131 * 64); copyb(Bs, br, 64);
    __syncthreads();
    dense_r(A, Wt, Bs);

    // Output layer: sigmoid(r @ wo + bo), 3 cols; one row per thread
    copyw(Wt, wo, 64 * 3); copyb(Bs, bo, 3);
    __syncthreads();
    if (tid < TILE_M) {
        float s0v = Bs[0], s1v = Bs[1], s2v = Bs[2];
#pragma unroll 8
        for (int k = 0; k < 64; k++) {
            float av = A[tid * A_W + k];
            s0v = fmaf(av, Wt[k * 3 + 0], s0v);
            s1v = fmaf(av, Wt[k * 3 + 1], s1v);
            s2v = fmaf(av, Wt[k * 3 + 2], s2v);
        }
        size_t o = (size_t)(s0 + tid) * 3;
        out[o + 0] = 1.f / (1.f + expf(-s0v));
        out[o + 1] = 1.f / (1.f + expf(-s1v));
        out[o + 2] = 1.f / (1.f + expf(-s2v));
    }
}

extern "C" void kernel_launch(void* const* d_in, const int* in_sizes, int n_in,
                              void* d_out, int out_size) {
    (void)in_sizes; (void)n_in; (void)out_size;
    const float* x  = (const float*)d_in[0];
    const float* w0 = (const float*)d_in[1];  const float* b0 = (const float*)d_in[2];
    const float* w1 = (const float*)d_in[3];  const float* b1 = (const float*)d_in[4];
    const float* w2 = (const float*)d_in[5];  const float* b2 = (const float*)d_in[6];
    const float* w3 = (const float*)d_in[7];  const float* b3 = (const float*)d_in[8];
    const float* wd = (const float*)d_in[9];  const float* bd = (const float*)d_in[10];
    const float* wf = (const float*)d_in[11]; const float* bf = (const float*)d_in[12];
    const float* wr = (const float*)d_in[13]; const float* br = (const float*)d_in[14];
    const float* wo = (const float*)d_in[15]; const float* bo = (const float*)d_in[16];
    float* out = (float*)d_out;

    cudaFuncSetAttribute(nerf_fused_kernel,
                         cudaFuncAttributeMaxDynamicSharedMemorySize, SMEM_BYTES);
    nerf_fused_kernel<<<S_TOTAL / TILE_M, NT, SMEM_BYTES>>>(
        x, w0, b0, w1, b1, w2, b2, w3, b3, wd, bd, wf, bf, wr, br, wo, bo, out);
}

// round 3
// speedup vs baseline: 1.0007x; 1.0007x over previous
#include <cuda_runtime.h>
#include <math.h>

#define N_RAYS   4096
#define N_SAMP   192
#define S_TOTAL  (N_RAYS * N_SAMP)   // 786432
#define TILE_M   128
#define A_W      135                  // 0-127 act | 128-130 pos | 131-133 view | 134 pad (odd width: no bank conflict on strided row loads)
#define NT       256

// smem: A tile + weight staging (max 131x128) + bias staging (128)
#define SMEM_FLOATS (TILE_M * A_W + 131 * 128 + 128)
#define SMEM_BYTES  (SMEM_FLOATS * 4)

__device__ __forceinline__ void copyw(float* dst, const float* __restrict__ src, int n) {
    const float4* s4 = (const float4*)src;
    float4* d4 = (float4*)dst;
    int n4 = n >> 2;
    for (int i = threadIdx.x; i < n4; i += NT) d4[i] = s4[i];
}
__device__ __forceinline__ void copyb(float* dst, const float* __restrict__ src, int n) {
    for (int i = threadIdx.x; i < n; i += NT) dst[i] = src[i];
}

// GEMM: [128 rows x K] @ [K x 128] + bias, ReLU, writeback into A cols 0..127.
// a_base: column offset in A where the K inputs start (128 for layer0 reading pos).
// skip:   added to A-column index for k>=128 (r-layer gathers view at cols 131-133).
__device__ __forceinline__ void dense128(float* A, const float* Wt, const float* Bs,
                                         int K, int a_base, int skip) {
    const int tx = threadIdx.x & 15;   // 16 col-groups of 8
    const int ty = threadIdx.x >> 4;   // 16 row-groups; rows ty + 16*j
    float acc[8][8];
#pragma unroll
    for (int i = 0; i < 8; i++) {
        float bv = Bs[tx * 8 + i];
#pragma unroll
        for (int j = 0; j < 8; j++) acc[j][i] = bv;
    }
#pragma unroll 4
    for (int k = 0; k < K; k++) {
        int ka = a_base + k + ((k >= 128) ? skip : 0);
        float a[8];
#pragma unroll
        for (int j = 0; j < 8; j++) a[j] = A[(ty + 16 * j) * A_W + ka];
        float4 b0v = *(const float4*)&Wt[k * 128 + tx * 8];
        float4 b1v = *(const float4*)&Wt[k * 128 + tx * 8 + 4];
        float b[8] = {b0v.x, b0v.y, b0v.z, b0v.w, b1v.x, b1v.y, b1v.z, b1v.w};
#pragma unroll
        for (int j = 0; j < 8; j++)
#pragma unroll
            for (int i = 0; i < 8; i++)
                acc[j][i] = fmaf(a[j], b[i], acc[j][i]);
    }
    __syncthreads();   // all reads of A / Wt done before overwrite
#pragma unroll
    for (int j = 0; j < 8; j++)
#pragma unroll
        for (int i = 0; i < 8; i++)
            A[(ty + 16 * j) * A_W + tx * 8 + i] = fmaxf(acc[j][i], 0.f);
    __syncthreads();
}

// r-layer: [128 x 131] @ [131 x 64] + br, ReLU -> A cols 0..63.
// Inputs: features at A cols 0..127, view at cols 131..133.
__device__ __forceinline__ void dense_r(float* A, const float* Wt, const float* Bs) {
    const int tx = threadIdx.x & 7;    // 8 col-groups of 8 (N=64)
    const int ty = threadIdx.x >> 3;   // 32 row-groups; rows ty + 32*j
    float acc[4][8];
#pragma unroll
    for (int i = 0; i < 8; i++) {
        float bv = Bs[tx * 8 + i];
#pragma unroll
        for (int j = 0; j < 4; j++) acc[j][i] = bv;
    }
#pragma unroll 4
    for (int k = 0; k < 131; k++) {
        int ka = (k < 128) ? k : k + 3;
        float a[4];
#pragma unroll
        for (int j = 0; j < 4; j++) a[j] = A[(ty + 32 * j) * A_W + ka];
        float4 b0v = *(const float4*)&Wt[k * 64 + tx * 8];
        float4 b1v = *(const float4*)&Wt[k * 64 + tx * 8 + 4];
        float b[8] = {b0v.x, b0v.y, b0v.z, b0v.w, b1v.x, b1v.y, b1v.z, b1v.w};
#pragma unroll
        for (int j = 0; j < 4; j++)
#pragma unroll
            for (int i = 0; i < 8; i++)
                acc[j][i] = fmaf(a[j], b[i], acc[j][i]);
    }
    __syncthreads();
#pragma unroll
    for (int j = 0; j < 4; j++)
#pragma unroll
        for (int i = 0; i < 8; i++)
            A[(ty + 32 * j) * A_W + tx * 8 + i] = fmaxf(acc[j][i], 0.f);
    __syncthreads();
}

__global__ void __launch_bounds__(NT, 1) nerf_fused_kernel(
    const float* __restrict__ x,
    const float* __restrict__ w0, const float* __restrict__ b0,
    const float* __restrict__ w1, const float* __restrict__ b1,
    const float* __restrict__ w2, const float* __restrict__ b2,
    const float* __restrict__ w3, const float* __restrict__ b3,
    const float* __restrict__ wd, const float* __restrict__ bd,
    const float* __restrict__ wf, const float* __restrict__ bf,
    const float* __restrict__ wr, const float* __restrict__ br,
    const float* __restrict__ wo, const float* __restrict__ bo,
    float* __restrict__ out) {
    extern __shared__ float smem[];
    float* A  = smem;                    // TILE_M * A_W
    float* Wt = A + TILE_M * A_W;        // up to 131*128
    float* Bs = Wt + 131 * 128;          // 128

    const int tid = threadIdx.x;
    const int s0 = blockIdx.x * TILE_M;

    // Stage x tile: pos -> cols 128..130, view -> cols 131..133
    for (int i = tid; i < TILE_M * 6; i += NT) {
        int r = i / 6, c = i % 6;
        A[r * A_W + 128 + c] = x[(size_t)(s0 + r) * 6 + c];
    }
    __syncthreads();

    // Layer 0: pos(3) -> 128
    copyw(Wt, w0, 3 * 128);  copyb(Bs, b0, 128);
    __syncthreads();
    dense128(A, Wt, Bs, 3, 128, 0);

    // Layer 1: 128 -> 128
    copyw(Wt, w1, 128 * 128); copyb(Bs, b1, 128);
    __syncthreads();
    dense128(A, Wt, Bs, 128, 0, 0);

    // Layer 2: [h, pos](131) -> 128  (pos contiguous at cols 128..130)
    copyw(Wt, w2, 131 * 128); copyb(Bs, b2, 128);
    __syncthreads();
    dense128(A, Wt, Bs, 131, 0, 0);

    // Layer 3: 128 -> 128
    copyw(Wt, w3, 128 * 128); copyb(Bs, b3, 128);
    __syncthreads();
    dense128(A, Wt, Bs, 128, 0, 0);

    // Stage wf (features) and wd (density head) together; bf -> Bs
    copyw(Wt, wf, 128 * 128);
    copyw(Wt + 128 * 128, wd, 128);
    copyb(Bs, bf, 128);
    __syncthreads();

    // Density: relu(h3 @ wd + bd), one row per thread (tid < 128), BEFORE A is overwritten
    if (tid < TILE_M) {
        const float* wds = Wt + 128 * 128;
        float d = bd[0];
#pragma unroll 8
        for (int k = 0; k < 128; k++) d = fmaf(A[tid * A_W + k], wds[k], d);
        out[3 * S_TOTAL + s0 + tid] = fmaxf(d, 0.f);
    }
    // Features: relu(h3 @ wf + bf) -> A cols 0..127 (internal sync orders density reads before writeback)
    dense128(A, Wt, Bs, 128, 0, 0);

    // r-layer: [features, view](131) -> 64
    copyw(Wt, wr, 131 * 64); copyb(Bs, br, 64);
    __syncthreads();
    dense_r(A, Wt, Bs);

    // Output layer: sigmoid(r @ wo + bo), 3 cols; one row per thread
    copyw(Wt, wo, 64 * 3); copyb(Bs, bo, 3);
    __syncthreads();
    if (tid < TILE_M) {
        float s0v = Bs[0], s1v = Bs[1], s2v = Bs[2];
#pragma unroll 8
        for (int k = 0; k < 64; k++) {
            float av = A[tid * A_W + k];
            s0v = fmaf(av, Wt[k * 3 + 0], s0v);
            s1v = fmaf(av, Wt[k * 3 + 1], s1v);
            s2v = fmaf(av, Wt[k * 3 + 2], s2v);
        }
        size_t o = (size_t)(s0 + tid) * 3;
        out[o + 0] = 1.f / (1.f + expf(-s0v));
        out[o + 1] = 1.f / (1.f + expf(-s1v));
        out[o + 2] = 1.f / (1.f + expf(-s2v));
    }
}

extern "C" void kernel_launch(void* const* d_in, const int* in_sizes, int n_in,
                              void* d_out, int out_size) {
    (void)in_sizes; (void)n_in; (void)out_size;
    const float* x  = (const float*)d_in[0];
    const float* w0 = (const float*)d_in[1];  const float* b0 = (const float*)d_in[2];
    const float* w1 = (const float*)d_in[3];  const float* b1 = (const float*)d_in[4];
    const float* w2 = (const float*)d_in[5];  const float* b2 = (const float*)d_in[6];
    const float* w3 = (const float*)d_in[7];  const float* b3 = (const float*)d_in[8];
    const float* wd = (const float*)d_in[9];  const float* bd = (const float*)d_in[10];
    const float* wf = (const float*)d_in[11]; const float* bf = (const float*)d_in[12];
    const float* wr = (const float*)d_in[13]; const float* br = (const float*)d_in[14];
    const float* wo = (const float*)d_in[15]; const float* bo = (const float*)d_in[16];
    float* out = (float*)d_out;

    cudaFuncSetAttribute(nerf_fused_kernel,
                         cudaFuncAttributeMaxDynamicSharedMemorySize, SMEM_BYTES);
    nerf_fused_kernel<<<S_TOTAL / TILE_M, NT, SMEM_BYTES>>>(
        x, w0, b0, w1, b1, w2, b2, w3, b3, wd, bd, wf, bf, wr, br, wo, bo, out);
}